// round 14
// baseline (speedup 1.0000x reference)
#include <cuda_runtime.h>
#include <cuda_fp16.h>
#include <math.h>
#include <stdint.h>

// Problem constants
#define BATCH   8
#define SPTS    2048
#define NPTS    8192
#define FDIM    256
#define CDIM    128
#define DIN     384
#define DH      512
#define DOUT    512
#define MROWS   (BATCH * NPTS)          // 65536
#define EPSF    1.1920929e-07f
#define BN_EPS  1e-5f
#define NOUT    512

// ---------------- scratch (device globals) ---------------------------------
__device__ __half g_A1[(size_t)MROWS * DIN];       // hi(X)            50 MB
__device__ __half g_A2[(size_t)MROWS * DH];        // hi(H')           67 MB
__device__ __half g_B1[(size_t)DH  * DIN];         // Bh W1^T
__device__ __half g_B2[(size_t)DOUT * DH];         // Bh W2^T
__device__ __half g_H[(size_t)MROWS * DH];         // GEMM out (fp16)  67 MB
__device__ float g_part[512 * 1024];               // per-rowblock col partials
__device__ float g_part2[32 * 1024];               // mid reduction
__device__ float g_stats[2 * 512 * 3];             // [layer][m|a|beta]

// hi-cast write of 4 floats
__device__ __forceinline__ void wcast4(__half* row, int c, float4 v) {
    __half2* p = (__half2*)(row + c);
    p[0] = __halves2half2(__float2half_rn(v.x), __float2half_rn(v.y));
    p[1] = __halves2half2(__float2half_rn(v.z), __float2half_rn(v.w));
}

// fast exact-GELU via erfc form: erfc(a) ~= p(t)*exp(-a^2) [A&S 7.1.26]
__device__ __forceinline__ float gelu_f(float y) {
    float u = 0.70710678118654752f * y;
    float a = fabsf(u);
    float t = __frcp_rn(fmaf(0.3275911f, a, 1.0f));
    float p = fmaf(1.061405429f, t, -1.453152027f);
    p = fmaf(p, t, 1.421413741f);
    p = fmaf(p, t, -0.284496736f);
    p = fmaf(p, t, 0.254829592f);
    p = p * t;
    float e = __expf(-u * u);
    float half_y_erfc = 0.5f * y * (p * e);
    return (y >= 0.0f) ? (y - half_y_erfc) : half_y_erfc;
}

// ======================= kernel 1: 3-NN interpolation ======================
// 2 points per thread (512 per block, grid 128 blocks): shared-candidate LDS
// amortized over 2 points; every SM carries at most 1 block (no imbalance).
// Per-point distance arithmetic and candidate order are IDENTICAL to the
// proven round-8 form: dot = FFMA(z,pz, FFMA(y,py, x*px));
//                      d   = FADD(FFMA(-2,dot,n1), n2)
__global__ __launch_bounds__(256)
void interp_kernel(const float* __restrict__ sxyz_g,
                   const float* __restrict__ spf,
                   const float* __restrict__ xyz,
                   const float* __restrict__ pf)
{
    __shared__ float4 s4[SPTS];
    __shared__ int   s_idx[512][3];
    __shared__ float s_w[512][3];

    const int b   = blockIdx.y;
    const int tid = threadIdx.x;

    const float* sb = sxyz_g + (size_t)b * SPTS * 3;
    for (int j = tid; j < SPTS; j += 256) {
        float x = sb[3 * j], y = sb[3 * j + 1], z = sb[3 * j + 2];
        float n2 = fmaf(z, z, fmaf(y, y, x * x));
        s4[j] = make_float4(x, y, z, n2);
    }
    __syncthreads();

    const int pbase = blockIdx.x * 512;
    const int pA = pbase + tid;
    const int pB = pA + 256;
    const int gA = b * NPTS + pA;
    const int gB = b * NPTS + pB;
    const float ax = xyz[(size_t)gA*3+0], ay = xyz[(size_t)gA*3+1], az = xyz[(size_t)gA*3+2];
    const float bx = xyz[(size_t)gB*3+0], by = xyz[(size_t)gB*3+1], bz = xyz[(size_t)gB*3+2];
    const float nA = fmaf(az, az, fmaf(ay, ay, ax * ax));
    const float nB = fmaf(bz, bz, fmaf(by, by, bx * bx));

    float e0 = 3.4e38f, e1 = 3.4e38f, e2 = 3.4e38f;
    int   j0 = 0, j1 = 0, j2 = 0;
    float f0 = 3.4e38f, f1 = 3.4e38f, f2 = 3.4e38f;
    int   k0 = 0, k1 = 0, k2 = 0;

    #pragma unroll 4
    for (int s = 0; s < SPTS; ++s) {
        float4 v = s4[s];
        float dotA = fmaf(v.z, az, fmaf(v.y, ay, v.x * ax));
        float dA   = __fadd_rn(fmaf(-2.0f, dotA, nA), v.w);
        float dotB = fmaf(v.z, bz, fmaf(v.y, by, v.x * bx));
        float dB   = __fadd_rn(fmaf(-2.0f, dotB, nB), v.w);
        if (dA < e2) {
            if (dA < e1) {
                e2 = e1; j2 = j1;
                if (dA < e0) { e1 = e0; j1 = j0; e0 = dA; j0 = s; }
                else         { e1 = dA; j1 = s; }
            } else { e2 = dA; j2 = s; }
        }
        if (dB < f2) {
            if (dB < f1) {
                f2 = f1; k2 = k1;
                if (dB < f0) { f1 = f0; k1 = k0; f0 = dB; k0 = s; }
                else         { f1 = dB; k1 = s; }
            } else { f2 = dB; k2 = s; }
        }
    }

    {
        float w0 = 1.0f / (fmaxf(e0, 0.0f) + EPSF);
        float w1 = 1.0f / (fmaxf(e1, 0.0f) + EPSF);
        float w2 = 1.0f / (fmaxf(e2, 0.0f) + EPSF);
        float inv = 1.0f / (w0 + w1 + w2);
        s_idx[tid][0] = j0; s_idx[tid][1] = j1; s_idx[tid][2] = j2;
        s_w[tid][0] = w0 * inv; s_w[tid][1] = w1 * inv; s_w[tid][2] = w2 * inv;
    }
    {
        float w0 = 1.0f / (fmaxf(f0, 0.0f) + EPSF);
        float w1 = 1.0f / (fmaxf(f1, 0.0f) + EPSF);
        float w2 = 1.0f / (fmaxf(f2, 0.0f) + EPSF);
        float inv = 1.0f / (w0 + w1 + w2);
        s_idx[tid + 256][0] = k0; s_idx[tid + 256][1] = k1; s_idx[tid + 256][2] = k2;
        s_w[tid + 256][0] = w0 * inv; s_w[tid + 256][1] = w1 * inv; s_w[tid + 256][2] = w2 * inv;
    }
    __syncthreads();

    const int warp = tid >> 5, lane = tid & 31;
    for (int q = warp; q < 512; q += 8) {
        const int pp   = pbase + q;
        const int grow = b * NPTS + pp;
        const float4* r0 = (const float4*)(spf + ((size_t)b*SPTS + s_idx[q][0]) * FDIM);
        const float4* r1 = (const float4*)(spf + ((size_t)b*SPTS + s_idx[q][1]) * FDIM);
        const float4* r2 = (const float4*)(spf + ((size_t)b*SPTS + s_idx[q][2]) * FDIM);
        const float a0 = s_w[q][0], a1 = s_w[q][1], a2 = s_w[q][2];
        __half* arow = g_A1 + (size_t)grow * DIN;

        const float4 pr4 = ((const float4*)(pf + (size_t)grow * CDIM))[lane];
        wcast4(arow, lane * 4, pr4);

        #pragma unroll
        for (int h = 0; h < 2; ++h) {
            int c4 = lane + h * 32;
            float4 va = r0[c4], vb = r1[c4], vc = r2[c4];
            float4 o;
            o.x = a0*va.x + a1*vb.x + a2*vc.x;
            o.y = a0*va.y + a1*vb.y + a2*vc.y;
            o.z = a0*va.z + a1*vb.z + a2*vc.z;
            o.w = a0*va.w + a1*vb.w + a2*vc.w;
            wcast4(arow, CDIM + c4 * 4, o);
        }
    }
}

// ============== kernel 1b: transpose + hi-cast weights =====================
__global__ __launch_bounds__(256)
void wsplit_kernel(const float* __restrict__ W, __half* __restrict__ Bp,
                   int K, int N)
{
    int i = blockIdx.x * 256 + threadIdx.x;
    if (i >= K * N) return;
    int n = i % N, k = i / N;
    float w = W[(size_t)k * N + n];
    Bp[(size_t)n * K + k] = __float2half_rn(w);
}

// ======================= kernel 2: HMMA fp16 GEMM ==========================
// C = Ah.Bh^T (fp16 out).  A [M,K], B [N,K] both hi fp16. BK=32,
// stage = A|B tiles 128x32 (row stride 40 halves), 4-stage cp.async ring.
// ldsm issued first after the barrier; next-stage cp.async after.
// Fused column-stat epilogue (exact, from fp32 accumulators).
#define LDSTR       40
#define TILE_BYTES  (128 * LDSTR * 2)   // 10240
#define TSTG        (2 * TILE_BYTES)    // 20480
#define GEMM_SMEM   (4 * TSTG)          // 81920

__device__ __forceinline__ void ldsm4(uint32_t* r, uint32_t addr) {
    asm volatile("ldmatrix.sync.aligned.m8n8.x4.shared.b16 {%0,%1,%2,%3}, [%4];"
                 : "=r"(r[0]), "=r"(r[1]), "=r"(r[2]), "=r"(r[3]) : "r"(addr));
}
__device__ __forceinline__ void mma16816(float* c, const uint32_t* a,
                                         uint32_t b0, uint32_t b1) {
    asm volatile(
        "mma.sync.aligned.m16n8k16.row.col.f32.f16.f16.f32 "
        "{%0,%1,%2,%3}, {%4,%5,%6,%7}, {%8,%9}, {%0,%1,%2,%3};"
        : "+f"(c[0]), "+f"(c[1]), "+f"(c[2]), "+f"(c[3])
        : "r"(a[0]), "r"(a[1]), "r"(a[2]), "r"(a[3]), "r"(b0), "r"(b1));
}
#define CPASYNC16(dst, src) \
    asm volatile("cp.async.cg.shared.global [%0], [%1], 16;" :: "r"(dst), "l"(src))
#define CPCOMMIT() asm volatile("cp.async.commit_group;" ::: "memory")

template<int K>
__global__ __launch_bounds__(256, 2)
void mma_gemm(const __half* __restrict__ A, const __half* __restrict__ B,
              __half* __restrict__ C, float* __restrict__ gpart)
{
    extern __shared__ __align__(16) char dsm[];

    constexpr int nch = K >> 5;

    const int tid  = threadIdx.x;
    const int lane = tid & 31;
    const int wid  = tid >> 5;
    const int warp_m = wid & 3;
    const int warp_n = wid >> 2;
    const size_t rowA = (size_t)blockIdx.y * 128;
    const size_t rowB = (size_t)blockIdx.x * 128;

    const int r0  = tid >> 1;
    const int ch0 = (tid & 1) * 2;
    const __half* gA = A + (rowA + r0) * K + ch0 * 8;
    const __half* gB = B + (rowB + r0) * K + ch0 * 8;
    const uint32_t sbase = (uint32_t)__cvta_generic_to_shared(dsm);
    const uint32_t sRow  = sbase + (uint32_t)(r0 * LDSTR + ch0 * 8) * 2;

    float acc[2][8][4];
    #pragma unroll
    for (int i = 0; i < 2; ++i)
        #pragma unroll
        for (int j = 0; j < 8; ++j)
            #pragma unroll
            for (int q = 0; q < 4; ++q) acc[i][j][q] = 0.0f;

    auto issue_step = [&](int s) {
        uint32_t off = (uint32_t)(s & 3) * TSTG;
        const __half* pa = gA + s * 32;
        const __half* pb = gB + s * 32;
        CPASYNC16(sRow + off,                    pa);
        CPASYNC16(sRow + off + 16,               pa + 8);
        CPASYNC16(sRow + off + TILE_BYTES,       pb);
        CPASYNC16(sRow + off + TILE_BYTES + 16,  pb + 8);
    };

    issue_step(0); CPCOMMIT();
    issue_step(1); CPCOMMIT();
    issue_step(2); CPCOMMIT();

    const int arow = warp_m * 32 + (lane & 15);
    const int acol = (lane >> 4) * 8;
    const uint32_t aAddr0 = sbase + (uint32_t)(arow * LDSTR + acol) * 2;
    const int brow = warp_n * 64 + (lane & 7) + ((lane >> 4) & 1) * 8;
    const int bcol = ((lane >> 3) & 1) * 8;
    const uint32_t bAddr0 = sbase + TILE_BYTES + (uint32_t)(brow * LDSTR + bcol) * 2;

    #pragma unroll
    for (int t = 0; t < nch; ++t) {
        asm volatile("cp.async.wait_group 2;" ::: "memory");
        __syncthreads();

        const uint32_t aB = aAddr0 + (t & 3) * TSTG;
        const uint32_t bB = bAddr0 + (t & 3) * TSTG;

        // ks = 0: ldsm first (starts the memory op immediately post-barrier)
        uint32_t ah0[2][4], bf0[4][4];
        #pragma unroll
        for (int im = 0; im < 2; ++im) ldsm4(ah0[im], aB + (im * 16 * LDSTR) * 2);
        #pragma unroll
        for (int ip = 0; ip < 4; ++ip) ldsm4(bf0[ip], bB + (ip * 16 * LDSTR) * 2);

        // next-stage global loads fly while ks0 fragments settle
        if (t + 3 < nch) issue_step(t + 3);
        CPCOMMIT();

        #pragma unroll
        for (int im = 0; im < 2; ++im)
            #pragma unroll
            for (int ip = 0; ip < 4; ++ip) {
                mma16816(acc[im][2 * ip],     ah0[im], bf0[ip][0], bf0[ip][1]);
                mma16816(acc[im][2 * ip + 1], ah0[im], bf0[ip][2], bf0[ip][3]);
            }

        // ks = 1 (reuses the ks0 fragment registers)
        #pragma unroll
        for (int im = 0; im < 2; ++im) ldsm4(ah0[im], aB + (im * 16 * LDSTR + 16) * 2);
        #pragma unroll
        for (int ip = 0; ip < 4; ++ip) ldsm4(bf0[ip], bB + (ip * 16 * LDSTR + 16) * 2);

        #pragma unroll
        for (int im = 0; im < 2; ++im)
            #pragma unroll
            for (int ip = 0; ip < 4; ++ip) {
                mma16816(acc[im][2 * ip],     ah0[im], bf0[ip][0], bf0[ip][1]);
                mma16816(acc[im][2 * ip + 1], ah0[im], bf0[ip][2], bf0[ip][3]);
            }
    }

    // ---- store C (fp16) ----
    const int crow = (int)rowA + warp_m * 32 + (lane >> 2);
    const int ccol = (int)rowB + warp_n * 64 + (lane & 3) * 2;
    #pragma unroll
    for (int im = 0; im < 2; ++im) {
        #pragma unroll
        for (int in = 0; in < 8; ++in) {
            __half* p0 = C + (size_t)(crow + im * 16) * NOUT + ccol + in * 8;
            __half* p1 = C + (size_t)(crow + im * 16 + 8) * NOUT + ccol + in * 8;
            *(__half2*)p0 = __halves2half2(__float2half_rn(acc[im][in][0]),
                                           __float2half_rn(acc[im][in][1]));
            *(__half2*)p1 = __halves2half2(__float2half_rn(acc[im][in][2]),
                                           __float2half_rn(acc[im][in][3]));
        }
    }

    // ---- fused column stats (from fp32 accumulators — exact) ----
    float cs[16], cq[16];
    #pragma unroll
    for (int in = 0; in < 8; ++in) {
        #pragma unroll
        for (int e = 0; e < 2; ++e) {
            float s = 0.0f, q = 0.0f;
            #pragma unroll
            for (int im = 0; im < 2; ++im) {
                float v0 = acc[im][in][e], v1 = acc[im][in][2 + e];
                s += v0 + v1;
                q += v0 * v0 + v1 * v1;
            }
            cs[in * 2 + e] = s;
            cq[in * 2 + e] = q;
        }
    }
    #pragma unroll
    for (int m = 4; m <= 16; m <<= 1) {
        #pragma unroll
        for (int i = 0; i < 16; ++i) {
            cs[i] += __shfl_xor_sync(0xFFFFFFFF, cs[i], m);
            cq[i] += __shfl_xor_sync(0xFFFFFFFF, cq[i], m);
        }
    }

    asm volatile("cp.async.wait_group 0;" ::: "memory");
    __syncthreads();
    float* sred = (float*)dsm;
    if (lane < 4) {
        #pragma unroll
        for (int i = 0; i < 16; ++i) {
            int cloc = (lane & 3) * 2 + (i & 1) + (i >> 1) * 8;
            sred[(wid * 64 + cloc) * 2 + 0] = cs[i];
            sred[(wid * 64 + cloc) * 2 + 1] = cq[i];
        }
    }
    __syncthreads();

    {
        const int col  = tid & 127;
        const int stat = tid >> 7;
        const int wn = col >> 6, cl = col & 63;
        float v = 0.0f;
        #pragma unroll
        for (int wm = 0; wm < 4; ++wm)
            v += sred[((wn * 4 + wm) * 64 + cl) * 2 + stat];
        gpart[(size_t)blockIdx.y * 1024 + stat * 512 + blockIdx.x * 128 + col] = v;
    }
}

// =================== kernel 3: hierarchical column stats ===================
__global__ __launch_bounds__(512)
void colstats_mid()
{
    const int c = threadIdx.x;
    const int blk = blockIdx.x;
    float s = 0.0f, q = 0.0f;
    #pragma unroll 4
    for (int b = 0; b < 16; ++b) {
        s += g_part[(size_t)(blk * 16 + b) * 1024 + c];
        q += g_part[(size_t)(blk * 16 + b) * 1024 + 512 + c];
    }
    g_part2[(size_t)blk * 1024 + c]       = s;
    g_part2[(size_t)blk * 1024 + 512 + c] = q;
}

__global__ __launch_bounds__(512)
void colstats_final(const float* __restrict__ gamma,
                    const float* __restrict__ beta, int layer)
{
    const int c = threadIdx.x;
    float s = 0.0f, q = 0.0f;
    #pragma unroll
    for (int b = 0; b < 32; ++b) {
        s += g_part2[(size_t)b * 1024 + c];
        q += g_part2[(size_t)b * 1024 + 512 + c];
    }
    const float invM = 1.0f / (float)MROWS;
    float m   = s * invM;
    float var = q * invM - m * m;
    float a   = gamma[c] * rsqrtf(var + BN_EPS);
    float* st = g_stats + (size_t)layer * 1536;
    st[c]        = m;
    st[512 + c]  = a;
    st[1024 + c] = beta[c];
}

// ============ kernel 4a: BN + GELU (fp16 H) -> hi fp16 into g_A2 ===========
__global__ __launch_bounds__(256)
void bn_gelu_split(const __half* __restrict__ H)
{
    const size_t idx = (size_t)blockIdx.x * blockDim.x + threadIdx.x;  // 4-half idx
    const size_t total = (size_t)MROWS * 512 / 4;
    if (idx >= total) return;
    const int c0 = (int)((idx & 127) * 4);
    const float* st = g_stats;

    const __half2* src = (const __half2*)(H + idx * 4);
    __half2 v0 = src[0], v1 = src[1];
    float o[4] = { __low2float(v0), __high2float(v0),
                   __low2float(v1), __high2float(v1) };
    #pragma unroll
    for (int j = 0; j < 4; ++j) {
        int c = c0 + j;
        float y = fmaf(o[j] - st[c], st[512 + c], st[1024 + c]);
        o[j] = gelu_f(y);
    }
    __half2* dst = (__half2*)(g_A2 + idx * 4);
    dst[0] = __halves2half2(__float2half_rn(o[0]), __float2half_rn(o[1]));
    dst[1] = __halves2half2(__float2half_rn(o[2]), __float2half_rn(o[3]));
}

// ============ kernel 4b: BN + GELU (fp16 H) -> fp32 final output ===========
__global__ __launch_bounds__(256)
void bn_gelu_out(const __half* __restrict__ H, float* __restrict__ O)
{
    const size_t idx = (size_t)blockIdx.x * blockDim.x + threadIdx.x;
    const size_t total = (size_t)MROWS * 512 / 4;
    if (idx >= total) return;
    const int c0 = (int)((idx & 127) * 4);
    const float* st = g_stats + 1536;

    const __half2* src = (const __half2*)(H + idx * 4);
    __half2 v0 = src[0], v1 = src[1];
    float o[4] = { __low2float(v0), __high2float(v0),
                   __low2float(v1), __high2float(v1) };
    #pragma unroll
    for (int j = 0; j < 4; ++j) {
        int c = c0 + j;
        float y = fmaf(o[j] - st[c], st[512 + c], st[1024 + c]);
        o[j] = gelu_f(y);
    }
    ((float4*)O)[idx] = make_float4(o[0], o[1], o[2], o[3]);
}

// ============================ launcher =====================================
extern "C" void kernel_launch(void* const* d_in, const int* in_sizes, int n_in,
                              void* d_out, int out_size)
{
    const float* sxyz = (const float*)d_in[0];
    const float* spf  = (const float*)d_in[1];
    const float* xyz  = (const float*)d_in[2];
    const float* pf   = (const float*)d_in[3];
    const float* W1   = (const float*)d_in[4];
    const float* g1   = (const float*)d_in[5];
    const float* b1   = (const float*)d_in[6];
    const float* W2   = (const float*)d_in[7];
    const float* g2   = (const float*)d_in[8];
    const float* b2   = (const float*)d_in[9];
    float* out = (float*)d_out;

    __half *pA1, *pA2, *pB1, *pB2, *pH;
    float *pPart;
    cudaGetSymbolAddress((void**)&pA1, g_A1);
    cudaGetSymbolAddress((void**)&pA2, g_A2);
    cudaGetSymbolAddress((void**)&pB1, g_B1);
    cudaGetSymbolAddress((void**)&pB2, g_B2);
    cudaGetSymbolAddress((void**)&pH,  g_H);
    cudaGetSymbolAddress((void**)&pPart, g_part);

    cudaFuncSetAttribute((const void*)mma_gemm<DIN>,
                         cudaFuncAttributeMaxDynamicSharedMemorySize, GEMM_SMEM);
    cudaFuncSetAttribute((const void*)mma_gemm<DH>,
                         cudaFuncAttributeMaxDynamicSharedMemorySize, GEMM_SMEM);

    // 0) weight transpose + hi cast
    wsplit_kernel<<<(DIN * DH + 255) / 256, 256>>>(W1, pB1, DIN, DH);
    wsplit_kernel<<<(DH * DOUT + 255) / 256, 256>>>(W2, pB2, DH, DOUT);

    // 1) 3-NN interpolation + concat -> hi fp16 g_A1 (2 pts/thread, 128 blocks)
    interp_kernel<<<dim3(NPTS / 512, BATCH), 256>>>(sxyz, spf, xyz, pf);

    // 2) GEMM1 (HMMA, 4-stage, fp16 out, fused stats): K = 384
    mma_gemm<DIN><<<dim3(DH / 128, MROWS / 128), 256, GEMM_SMEM>>>(pA1, pB1, pH, pPart);

    // 3) stats reduce + BN+GELU -> hi fp16 g_A2
    colstats_mid<<<32, 512>>>();
    colstats_final<<<1, 512>>>(g1, b1, 0);
    bn_gelu_split<<<(MROWS * 512 / 4 + 255) / 256, 256>>>(pH);

    // 4) GEMM2 (HMMA, 4-stage, fp16 out, fused stats): K = 512
    mma_gemm<DH><<<dim3(DOUT / 128, MROWS / 128), 256, GEMM_SMEM>>>(pA2, pB2, pH, pPart);

    // 5) stats reduce + BN+GELU -> fp32 out
    colstats_mid<<<32, 512>>>();
    colstats_final<<<1, 512>>>(g2, b2, 1);
    bn_gelu_out<<<(MROWS * 512 / 4 + 255) / 256, 256>>>(pH, out);
}

// round 15
// speedup vs baseline: 1.1233x; 1.1233x over previous
#include <cuda_runtime.h>
#include <cuda_fp16.h>
#include <math.h>
#include <stdint.h>

// Problem constants
#define BATCH   8
#define SPTS    2048
#define NPTS    8192
#define FDIM    256
#define CDIM    128
#define DIN     384
#define DH      512
#define DOUT    512
#define MROWS   (BATCH * NPTS)          // 65536
#define EPSF    1.1920929e-07f
#define BN_EPS  1e-5f
#define NOUT    512

// ---------------- scratch (device globals) ---------------------------------
__device__ __half g_A1[(size_t)MROWS * DIN];       // hi(X)            50 MB
__device__ __half g_A2[(size_t)MROWS * DH];        // hi(H')           67 MB
__device__ __half g_B1[(size_t)DH  * DIN];         // Bh W1^T
__device__ __half g_B2[(size_t)DOUT * DH];         // Bh W2^T
__device__ __half g_H[(size_t)MROWS * DH];         // GEMM out (fp16)  67 MB
__device__ float g_part[512 * 1024];               // per-rowblock col partials
__device__ float g_part2[32 * 1024];               // mid reduction
__device__ float g_stats[2 * 512 * 3];             // [layer][m|a|beta]

// hi-cast write of 4 floats
__device__ __forceinline__ void wcast4(__half* row, int c, float4 v) {
    __half2* p = (__half2*)(row + c);
    p[0] = __halves2half2(__float2half_rn(v.x), __float2half_rn(v.y));
    p[1] = __halves2half2(__float2half_rn(v.z), __float2half_rn(v.w));
}

// fast exact-GELU via erfc form: erfc(a) ~= p(t)*exp(-a^2) [A&S 7.1.26]
__device__ __forceinline__ float gelu_f(float y) {
    float u = 0.70710678118654752f * y;
    float a = fabsf(u);
    float t = __frcp_rn(fmaf(0.3275911f, a, 1.0f));
    float p = fmaf(1.061405429f, t, -1.453152027f);
    p = fmaf(p, t, 1.421413741f);
    p = fmaf(p, t, -0.284496736f);
    p = fmaf(p, t, 0.254829592f);
    p = p * t;
    float e = __expf(-u * u);
    float half_y_erfc = 0.5f * y * (p * e);
    return (y >= 0.0f) ? (y - half_y_erfc) : half_y_erfc;
}

// ======================= kernel 1: 3-NN interpolation ======================
// PROVEN round-12/13 shape: 1 point/thread, 256 threads, 256 blocks/batch.
// Distance arithmetic matches the reference-selection-exact association:
//   dot = FFMA(z,pz, FFMA(y,py, x*px));  d = FADD(FFMA(-2,dot,n1), n2)
__global__ __launch_bounds__(256)
void interp_kernel(const float* __restrict__ sxyz_g,
                   const float* __restrict__ spf,
                   const float* __restrict__ xyz,
                   const float* __restrict__ pf)
{
    __shared__ float4 s4[SPTS];
    __shared__ int   s_idx[256][3];
    __shared__ float s_w[256][3];

    const int b   = blockIdx.y;
    const int tid = threadIdx.x;

    const float* sb = sxyz_g + (size_t)b * SPTS * 3;
    for (int j = tid; j < SPTS; j += 256) {
        float x = sb[3 * j], y = sb[3 * j + 1], z = sb[3 * j + 2];
        float n2 = fmaf(z, z, fmaf(y, y, x * x));
        s4[j] = make_float4(x, y, z, n2);
    }
    __syncthreads();

    const int p  = blockIdx.x * 256 + tid;
    const int gp = b * NPTS + p;
    const float px = xyz[(size_t)gp*3 + 0];
    const float py = xyz[(size_t)gp*3 + 1];
    const float pz = xyz[(size_t)gp*3 + 2];
    const float n1 = fmaf(pz, pz, fmaf(py, py, px * px));

    float d0 = 3.4e38f, d1 = 3.4e38f, d2 = 3.4e38f;
    int   i0 = 0, i1 = 0, i2 = 0;

    #pragma unroll 4
    for (int s = 0; s < SPTS; ++s) {
        float4 v = s4[s];
        float dot = fmaf(v.z, pz, fmaf(v.y, py, v.x * px));
        float d   = __fadd_rn(fmaf(-2.0f, dot, n1), v.w);
        if (d < d2) {
            if (d < d1) {
                d2 = d1; i2 = i1;
                if (d < d0) { d1 = d0; i1 = i0; d0 = d; i0 = s; }
                else        { d1 = d;  i1 = s; }
            } else { d2 = d; i2 = s; }
        }
    }

    float w0 = 1.0f / (fmaxf(d0, 0.0f) + EPSF);
    float w1 = 1.0f / (fmaxf(d1, 0.0f) + EPSF);
    float w2 = 1.0f / (fmaxf(d2, 0.0f) + EPSF);
    float inv = 1.0f / (w0 + w1 + w2);
    s_idx[tid][0] = i0; s_idx[tid][1] = i1; s_idx[tid][2] = i2;
    s_w[tid][0] = w0 * inv; s_w[tid][1] = w1 * inv; s_w[tid][2] = w2 * inv;
    __syncthreads();

    const int warp = tid >> 5, lane = tid & 31;
    for (int q = warp; q < 256; q += 8) {
        const int pp   = blockIdx.x * 256 + q;
        const int grow = b * NPTS + pp;
        const float4* r0 = (const float4*)(spf + ((size_t)b*SPTS + s_idx[q][0]) * FDIM);
        const float4* r1 = (const float4*)(spf + ((size_t)b*SPTS + s_idx[q][1]) * FDIM);
        const float4* r2 = (const float4*)(spf + ((size_t)b*SPTS + s_idx[q][2]) * FDIM);
        const float a0 = s_w[q][0], a1 = s_w[q][1], a2 = s_w[q][2];
        __half* arow = g_A1 + (size_t)grow * DIN;

        const float4 pr4 = ((const float4*)(pf + (size_t)grow * CDIM))[lane];
        wcast4(arow, lane * 4, pr4);

        #pragma unroll
        for (int h = 0; h < 2; ++h) {
            int c4 = lane + h * 32;
            float4 va = r0[c4], vb = r1[c4], vc = r2[c4];
            float4 o;
            o.x = a0*va.x + a1*vb.x + a2*vc.x;
            o.y = a0*va.y + a1*vb.y + a2*vc.y;
            o.z = a0*va.z + a1*vb.z + a2*vc.z;
            o.w = a0*va.w + a1*vb.w + a2*vc.w;
            wcast4(arow, CDIM + c4 * 4, o);
        }
    }
}

// ============== kernel 1b: transpose + hi-cast weights =====================
__global__ __launch_bounds__(256)
void wsplit_kernel(const float* __restrict__ W, __half* __restrict__ Bp,
                   int K, int N)
{
    int i = blockIdx.x * 256 + threadIdx.x;
    if (i >= K * N) return;
    int n = i % N, k = i / N;
    float w = W[(size_t)k * N + n];
    Bp[(size_t)n * K + k] = __float2half_rn(w);
}

// ======================= kernel 2: HMMA fp16 GEMM ==========================
// C = Ah.Bh^T (fp16 out).  A [M,K], B [N,K] both hi fp16. BK=32,
// stage = A|B tiles 128x32 (row stride 40 halves), 4-stage cp.async ring.
// Mainloop ordering (round-14 verified): ldsm ks0 -> next-stage cp.async ->
// MMA ks0 -> ldsm ks1 -> MMA ks1.
// Fused column-stat epilogue (exact, from fp32 accumulators).
#define LDSTR       40
#define TILE_BYTES  (128 * LDSTR * 2)   // 10240
#define TSTG        (2 * TILE_BYTES)    // 20480
#define GEMM_SMEM   (4 * TSTG)          // 81920

__device__ __forceinline__ void ldsm4(uint32_t* r, uint32_t addr) {
    asm volatile("ldmatrix.sync.aligned.m8n8.x4.shared.b16 {%0,%1,%2,%3}, [%4];"
                 : "=r"(r[0]), "=r"(r[1]), "=r"(r[2]), "=r"(r[3]) : "r"(addr));
}
__device__ __forceinline__ void mma16816(float* c, const uint32_t* a,
                                         uint32_t b0, uint32_t b1) {
    asm volatile(
        "mma.sync.aligned.m16n8k16.row.col.f32.f16.f16.f32 "
        "{%0,%1,%2,%3}, {%4,%5,%6,%7}, {%8,%9}, {%0,%1,%2,%3};"
        : "+f"(c[0]), "+f"(c[1]), "+f"(c[2]), "+f"(c[3])
        : "r"(a[0]), "r"(a[1]), "r"(a[2]), "r"(a[3]), "r"(b0), "r"(b1));
}
#define CPASYNC16(dst, src) \
    asm volatile("cp.async.cg.shared.global [%0], [%1], 16;" :: "r"(dst), "l"(src))
#define CPCOMMIT() asm volatile("cp.async.commit_group;" ::: "memory")

template<int K>
__global__ __launch_bounds__(256, 2)
void mma_gemm(const __half* __restrict__ A, const __half* __restrict__ B,
              __half* __restrict__ C, float* __restrict__ gpart)
{
    extern __shared__ __align__(16) char dsm[];

    constexpr int nch = K >> 5;

    const int tid  = threadIdx.x;
    const int lane = tid & 31;
    const int wid  = tid >> 5;
    const int warp_m = wid & 3;
    const int warp_n = wid >> 2;
    const size_t rowA = (size_t)blockIdx.y * 128;
    const size_t rowB = (size_t)blockIdx.x * 128;

    const int r0  = tid >> 1;
    const int ch0 = (tid & 1) * 2;
    const __half* gA = A + (rowA + r0) * K + ch0 * 8;
    const __half* gB = B + (rowB + r0) * K + ch0 * 8;
    const uint32_t sbase = (uint32_t)__cvta_generic_to_shared(dsm);
    const uint32_t sRow  = sbase + (uint32_t)(r0 * LDSTR + ch0 * 8) * 2;

    float acc[2][8][4];
    #pragma unroll
    for (int i = 0; i < 2; ++i)
        #pragma unroll
        for (int j = 0; j < 8; ++j)
            #pragma unroll
            for (int q = 0; q < 4; ++q) acc[i][j][q] = 0.0f;

    auto issue_step = [&](int s) {
        uint32_t off = (uint32_t)(s & 3) * TSTG;
        const __half* pa = gA + s * 32;
        const __half* pb = gB + s * 32;
        CPASYNC16(sRow + off,                    pa);
        CPASYNC16(sRow + off + 16,               pa + 8);
        CPASYNC16(sRow + off + TILE_BYTES,       pb);
        CPASYNC16(sRow + off + TILE_BYTES + 16,  pb + 8);
    };

    issue_step(0); CPCOMMIT();
    issue_step(1); CPCOMMIT();
    issue_step(2); CPCOMMIT();

    const int arow = warp_m * 32 + (lane & 15);
    const int acol = (lane >> 4) * 8;
    const uint32_t aAddr0 = sbase + (uint32_t)(arow * LDSTR + acol) * 2;
    const int brow = warp_n * 64 + (lane & 7) + ((lane >> 4) & 1) * 8;
    const int bcol = ((lane >> 3) & 1) * 8;
    const uint32_t bAddr0 = sbase + TILE_BYTES + (uint32_t)(brow * LDSTR + bcol) * 2;

    #pragma unroll
    for (int t = 0; t < nch; ++t) {
        asm volatile("cp.async.wait_group 2;" ::: "memory");
        __syncthreads();

        const uint32_t aB = aAddr0 + (t & 3) * TSTG;
        const uint32_t bB = bAddr0 + (t & 3) * TSTG;

        // ks = 0: ldsm first (starts the memory op immediately post-barrier)
        uint32_t ah0[2][4], bf0[4][4];
        #pragma unroll
        for (int im = 0; im < 2; ++im) ldsm4(ah0[im], aB + (im * 16 * LDSTR) * 2);
        #pragma unroll
        for (int ip = 0; ip < 4; ++ip) ldsm4(bf0[ip], bB + (ip * 16 * LDSTR) * 2);

        // next-stage global loads fly while ks0 fragments settle
        if (t + 3 < nch) issue_step(t + 3);
        CPCOMMIT();

        #pragma unroll
        for (int im = 0; im < 2; ++im)
            #pragma unroll
            for (int ip = 0; ip < 4; ++ip) {
                mma16816(acc[im][2 * ip],     ah0[im], bf0[ip][0], bf0[ip][1]);
                mma16816(acc[im][2 * ip + 1], ah0[im], bf0[ip][2], bf0[ip][3]);
            }

        // ks = 1 (reuses the ks0 fragment registers)
        #pragma unroll
        for (int im = 0; im < 2; ++im) ldsm4(ah0[im], aB + (im * 16 * LDSTR + 16) * 2);
        #pragma unroll
        for (int ip = 0; ip < 4; ++ip) ldsm4(bf0[ip], bB + (ip * 16 * LDSTR + 16) * 2);

        #pragma unroll
        for (int im = 0; im < 2; ++im)
            #pragma unroll
            for (int ip = 0; ip < 4; ++ip) {
                mma16816(acc[im][2 * ip],     ah0[im], bf0[ip][0], bf0[ip][1]);
                mma16816(acc[im][2 * ip + 1], ah0[im], bf0[ip][2], bf0[ip][3]);
            }
    }

    // ---- store C (fp16) ----
    const int crow = (int)rowA + warp_m * 32 + (lane >> 2);
    const int ccol = (int)rowB + warp_n * 64 + (lane & 3) * 2;
    #pragma unroll
    for (int im = 0; im < 2; ++im) {
        #pragma unroll
        for (int in = 0; in < 8; ++in) {
            __half* p0 = C + (size_t)(crow + im * 16) * NOUT + ccol + in * 8;
            __half* p1 = C + (size_t)(crow + im * 16 + 8) * NOUT + ccol + in * 8;
            *(__half2*)p0 = __halves2half2(__float2half_rn(acc[im][in][0]),
                                           __float2half_rn(acc[im][in][1]));
            *(__half2*)p1 = __halves2half2(__float2half_rn(acc[im][in][2]),
                                           __float2half_rn(acc[im][in][3]));
        }
    }

    // ---- fused column stats (from fp32 accumulators — exact) ----
    float cs[16], cq[16];
    #pragma unroll
    for (int in = 0; in < 8; ++in) {
        #pragma unroll
        for (int e = 0; e < 2; ++e) {
            float s = 0.0f, q = 0.0f;
            #pragma unroll
            for (int im = 0; im < 2; ++im) {
                float v0 = acc[im][in][e], v1 = acc[im][in][2 + e];
                s += v0 + v1;
                q += v0 * v0 + v1 * v1;
            }
            cs[in * 2 + e] = s;
            cq[in * 2 + e] = q;
        }
    }
    #pragma unroll
    for (int m = 4; m <= 16; m <<= 1) {
        #pragma unroll
        for (int i = 0; i < 16; ++i) {
            cs[i] += __shfl_xor_sync(0xFFFFFFFF, cs[i], m);
            cq[i] += __shfl_xor_sync(0xFFFFFFFF, cq[i], m);
        }
    }

    asm volatile("cp.async.wait_group 0;" ::: "memory");
    __syncthreads();
    float* sred = (float*)dsm;
    if (lane < 4) {
        #pragma unroll
        for (int i = 0; i < 16; ++i) {
            int cloc = (lane & 3) * 2 + (i & 1) + (i >> 1) * 8;
            sred[(wid * 64 + cloc) * 2 + 0] = cs[i];
            sred[(wid * 64 + cloc) * 2 + 1] = cq[i];
        }
    }
    __syncthreads();

    {
        const int col  = tid & 127;
        const int stat = tid >> 7;
        const int wn = col >> 6, cl = col & 63;
        float v = 0.0f;
        #pragma unroll
        for (int wm = 0; wm < 4; ++wm)
            v += sred[((wn * 4 + wm) * 64 + cl) * 2 + stat];
        gpart[(size_t)blockIdx.y * 1024 + stat * 512 + blockIdx.x * 128 + col] = v;
    }
}

// =================== kernel 3: hierarchical column stats ===================
__global__ __launch_bounds__(512)
void colstats_mid()
{
    const int c = threadIdx.x;
    const int blk = blockIdx.x;
    float s = 0.0f, q = 0.0f;
    #pragma unroll 4
    for (int b = 0; b < 16; ++b) {
        s += g_part[(size_t)(blk * 16 + b) * 1024 + c];
        q += g_part[(size_t)(blk * 16 + b) * 1024 + 512 + c];
    }
    g_part2[(size_t)blk * 1024 + c]       = s;
    g_part2[(size_t)blk * 1024 + 512 + c] = q;
}

__global__ __launch_bounds__(512)
void colstats_final(const float* __restrict__ gamma,
                    const float* __restrict__ beta, int layer)
{
    const int c = threadIdx.x;
    float s = 0.0f, q = 0.0f;
    #pragma unroll
    for (int b = 0; b < 32; ++b) {
        s += g_part2[(size_t)b * 1024 + c];
        q += g_part2[(size_t)b * 1024 + 512 + c];
    }
    const float invM = 1.0f / (float)MROWS;
    float m   = s * invM;
    float var = q * invM - m * m;
    float a   = gamma[c] * rsqrtf(var + BN_EPS);
    float* st = g_stats + (size_t)layer * 1536;
    st[c]        = m;
    st[512 + c]  = a;
    st[1024 + c] = beta[c];
}

// ============ kernel 4a: BN + GELU (fp16 H) -> hi fp16 into g_A2 ===========
__global__ __launch_bounds__(256)
void bn_gelu_split(const __half* __restrict__ H)
{
    const size_t idx = (size_t)blockIdx.x * blockDim.x + threadIdx.x;  // 4-half idx
    const size_t total = (size_t)MROWS * 512 / 4;
    if (idx >= total) return;
    const int c0 = (int)((idx & 127) * 4);
    const float* st = g_stats;

    const __half2* src = (const __half2*)(H + idx * 4);
    __half2 v0 = src[0], v1 = src[1];
    float o[4] = { __low2float(v0), __high2float(v0),
                   __low2float(v1), __high2float(v1) };
    #pragma unroll
    for (int j = 0; j < 4; ++j) {
        int c = c0 + j;
        float y = fmaf(o[j] - st[c], st[512 + c], st[1024 + c]);
        o[j] = gelu_f(y);
    }
    __half2* dst = (__half2*)(g_A2 + idx * 4);
    dst[0] = __halves2half2(__float2half_rn(o[0]), __float2half_rn(o[1]));
    dst[1] = __halves2half2(__float2half_rn(o[2]), __float2half_rn(o[3]));
}

// ============ kernel 4b: BN + GELU (fp16 H) -> fp32 final output ===========
__global__ __launch_bounds__(256)
void bn_gelu_out(const __half* __restrict__ H, float* __restrict__ O)
{
    const size_t idx = (size_t)blockIdx.x * blockDim.x + threadIdx.x;
    const size_t total = (size_t)MROWS * 512 / 4;
    if (idx >= total) return;
    const int c0 = (int)((idx & 127) * 4);
    const float* st = g_stats + 1536;

    const __half2* src = (const __half2*)(H + idx * 4);
    __half2 v0 = src[0], v1 = src[1];
    float o[4] = { __low2float(v0), __high2float(v0),
                   __low2float(v1), __high2float(v1) };
    #pragma unroll
    for (int j = 0; j < 4; ++j) {
        int c = c0 + j;
        float y = fmaf(o[j] - st[c], st[512 + c], st[1024 + c]);
        o[j] = gelu_f(y);
    }
    ((float4*)O)[idx] = make_float4(o[0], o[1], o[2], o[3]);
}

// ============================ launcher =====================================
extern "C" void kernel_launch(void* const* d_in, const int* in_sizes, int n_in,
                              void* d_out, int out_size)
{
    const float* sxyz = (const float*)d_in[0];
    const float* spf  = (const float*)d_in[1];
    const float* xyz  = (const float*)d_in[2];
    const float* pf   = (const float*)d_in[3];
    const float* W1   = (const float*)d_in[4];
    const float* g1   = (const float*)d_in[5];
    const float* b1   = (const float*)d_in[6];
    const float* W2   = (const float*)d_in[7];
    const float* g2   = (const float*)d_in[8];
    const float* b2   = (const float*)d_in[9];
    float* out = (float*)d_out;

    __half *pA1, *pA2, *pB1, *pB2, *pH;
    float *pPart;
    cudaGetSymbolAddress((void**)&pA1, g_A1);
    cudaGetSymbolAddress((void**)&pA2, g_A2);
    cudaGetSymbolAddress((void**)&pB1, g_B1);
    cudaGetSymbolAddress((void**)&pB2, g_B2);
    cudaGetSymbolAddress((void**)&pH,  g_H);
    cudaGetSymbolAddress((void**)&pPart, g_part);

    cudaFuncSetAttribute((const void*)mma_gemm<DIN>,
                         cudaFuncAttributeMaxDynamicSharedMemorySize, GEMM_SMEM);
    cudaFuncSetAttribute((const void*)mma_gemm<DH>,
                         cudaFuncAttributeMaxDynamicSharedMemorySize, GEMM_SMEM);

    // 0) weight transpose + hi cast
    wsplit_kernel<<<(DIN * DH + 255) / 256, 256>>>(W1, pB1, DIN, DH);
    wsplit_kernel<<<(DH * DOUT + 255) / 256, 256>>>(W2, pB2, DH, DOUT);

    // 1) 3-NN interpolation + concat -> hi fp16 g_A1 (1 pt/thread, proven)
    interp_kernel<<<dim3(NPTS / 256, BATCH), 256>>>(sxyz, spf, xyz, pf);

    // 2) GEMM1 (HMMA, 4-stage, ldsm-first, fp16 out, fused stats): K = 384
    mma_gemm<DIN><<<dim3(DH / 128, MROWS / 128), 256, GEMM_SMEM>>>(pA1, pB1, pH, pPart);

    // 3) stats reduce + BN+GELU -> hi fp16 g_A2
    colstats_mid<<<32, 512>>>();
    colstats_final<<<1, 512>>>(g1, b1, 0);
    bn_gelu_split<<<(MROWS * 512 / 4 + 255) / 256, 256>>>(pH);

    // 4) GEMM2 (HMMA, 4-stage, ldsm-first, fp16 out, fused stats): K = 512
    mma_gemm<DH><<<dim3(DOUT / 128, MROWS / 128), 256, GEMM_SMEM>>>(pA2, pB2, pH, pPart);

    // 5) stats reduce + BN+GELU -> fp32 out
    colstats_mid<<<32, 512>>>();
    colstats_final<<<1, 512>>>(g2, b2, 1);
    bn_gelu_out<<<(MROWS * 512 / 4 + 255) / 256, 256>>>(pH, out);
}